// round 12
// baseline (speedup 1.0000x reference)
#include <cuda_runtime.h>
#include <math_constants.h>
#include <math.h>
#include <cstdint>

#define TOKENS 16384
#define HIDDEN 7168
#define NEXP   256
#define TOPK   8
#define BM     128
#define BN     128
#define BK     16
#define NK     (HIDDEN / BK)   // 448
#define TAU    1e-4f

__device__ float g_logits[(size_t)TOKENS * NEXP];
__device__ int   g_nflag;
__device__ int   g_flagged[TOKENS];

__global__ void init_flags_kernel() { g_nflag = 0; }

// ---------------------------------------------------------------------------
// Kernel: fp32 SGEMM — R1's exact machinery (the 1337us kernel), BK 8->16.
// C[m][n] = sum_k A[m][k] * B[n][k]. 128x128 tile, 256 threads, 8x8/thread,
// LDG->reg->STS double buffer, one sync per chunk.
// ---------------------------------------------------------------------------
__global__ __launch_bounds__(256)
void gemm_kernel(const float* __restrict__ A, const float* __restrict__ B)
{
    __shared__ float As[2][BK][BM];
    __shared__ float Bs[2][BK][BN];

    const int bm  = blockIdx.x * BM;
    const int bn  = blockIdx.y * BN;
    const int tid = threadIdx.x;
    const int tx  = tid & 15;   // 0..15 -> expert cols
    const int ty  = tid >> 4;   // 0..15 -> token rows

    // Global-load mapping: each thread loads two float4 (8 k) of A and of B
    const int ldrow = tid >> 1;        // 0..127
    const int ldcol = (tid & 1) * 8;   // 0 or 8

    const float* Aptr = A + (size_t)(bm + ldrow) * HIDDEN + ldcol;
    const float* Bptr = B + (size_t)(bn + ldrow) * HIDDEN + ldcol;

    float acc[8][8];
    #pragma unroll
    for (int i = 0; i < 8; i++)
        #pragma unroll
        for (int j = 0; j < 8; j++) acc[i][j] = 0.0f;

    // Preload tile 0
    {
        float4 a0 = *(const float4*)Aptr;
        float4 a1 = *(const float4*)(Aptr + 4);
        float4 b0 = *(const float4*)Bptr;
        float4 b1 = *(const float4*)(Bptr + 4);
        As[0][ldcol + 0][ldrow] = a0.x; As[0][ldcol + 1][ldrow] = a0.y;
        As[0][ldcol + 2][ldrow] = a0.z; As[0][ldcol + 3][ldrow] = a0.w;
        As[0][ldcol + 4][ldrow] = a1.x; As[0][ldcol + 5][ldrow] = a1.y;
        As[0][ldcol + 6][ldrow] = a1.z; As[0][ldcol + 7][ldrow] = a1.w;
        Bs[0][ldcol + 0][ldrow] = b0.x; Bs[0][ldcol + 1][ldrow] = b0.y;
        Bs[0][ldcol + 2][ldrow] = b0.z; Bs[0][ldcol + 3][ldrow] = b0.w;
        Bs[0][ldcol + 4][ldrow] = b1.x; Bs[0][ldcol + 5][ldrow] = b1.y;
        Bs[0][ldcol + 6][ldrow] = b1.z; Bs[0][ldcol + 7][ldrow] = b1.w;
    }
    __syncthreads();

    int buf = 0;
    for (int kt = 0; kt < NK; kt++) {
        float4 na0, na1, nb0, nb1;
        const bool has_next = (kt + 1 < NK);
        if (has_next) {
            na0 = *(const float4*)(Aptr + (size_t)(kt + 1) * BK);
            na1 = *(const float4*)(Aptr + (size_t)(kt + 1) * BK + 4);
            nb0 = *(const float4*)(Bptr + (size_t)(kt + 1) * BK);
            nb1 = *(const float4*)(Bptr + (size_t)(kt + 1) * BK + 4);
        }
        #pragma unroll
        for (int k = 0; k < BK; k++) {
            float ar[8], br[8];
            *(float4*)&ar[0] = *(const float4*)&As[buf][k][ty * 4];
            *(float4*)&ar[4] = *(const float4*)&As[buf][k][ty * 4 + 64];
            *(float4*)&br[0] = *(const float4*)&Bs[buf][k][tx * 4];
            *(float4*)&br[4] = *(const float4*)&Bs[buf][k][tx * 4 + 64];
            #pragma unroll
            for (int i = 0; i < 8; i++)
                #pragma unroll
                for (int j = 0; j < 8; j++)
                    acc[i][j] += ar[i] * br[j];
        }
        if (has_next) {
            const int nbuf = buf ^ 1;
            As[nbuf][ldcol + 0][ldrow] = na0.x; As[nbuf][ldcol + 1][ldrow] = na0.y;
            As[nbuf][ldcol + 2][ldrow] = na0.z; As[nbuf][ldcol + 3][ldrow] = na0.w;
            As[nbuf][ldcol + 4][ldrow] = na1.x; As[nbuf][ldcol + 5][ldrow] = na1.y;
            As[nbuf][ldcol + 6][ldrow] = na1.z; As[nbuf][ldcol + 7][ldrow] = na1.w;
            Bs[nbuf][ldcol + 0][ldrow] = nb0.x; Bs[nbuf][ldcol + 1][ldrow] = nb0.y;
            Bs[nbuf][ldcol + 2][ldrow] = nb0.z; Bs[nbuf][ldcol + 3][ldrow] = nb0.w;
            Bs[nbuf][ldcol + 4][ldrow] = nb1.x; Bs[nbuf][ldcol + 5][ldrow] = nb1.y;
            Bs[nbuf][ldcol + 6][ldrow] = nb1.z; Bs[nbuf][ldcol + 7][ldrow] = nb1.w;
            __syncthreads();
            buf = nbuf;
        }
    }

    // Epilogue: rows ty*4+{0..3}, ty*4+64+{0..3}; cols tx*4+{0..3}, tx*4+64+{0..3}
    #pragma unroll
    for (int i = 0; i < 8; i++) {
        const int r = bm + ty * 4 + ((i < 4) ? i : (60 + i));  // i>=4 -> 64+(i-4)
        float* C = g_logits + (size_t)r * NEXP + bn;
        *(float4*)(C + tx * 4)      = make_float4(acc[i][0], acc[i][1], acc[i][2], acc[i][3]);
        *(float4*)(C + tx * 4 + 64) = make_float4(acc[i][4], acc[i][5], acc[i][6], acc[i][7]);
    }
}

// ---------------------------------------------------------------------------
// route_one: reference-exact routing for one token (validated R4-R11).
// ---------------------------------------------------------------------------
__device__ __forceinline__ void route_one(const float* __restrict__ row,
                                          const float* __restrict__ bias,
                                          float* __restrict__ out,
                                          int write_idx, int token, int lane,
                                          int do_flag)
{
    const unsigned FULL = 0xffffffffu;

    float4 l0 = *(const float4*)(row + lane * 8);
    float4 l1 = *(const float4*)(row + lane * 8 + 4);
    float4 b0 = *(const float4*)(bias + lane * 8);
    float4 b1 = *(const float4*)(bias + lane * 8 + 4);

    float lv[8] = {l0.x, l0.y, l0.z, l0.w, l1.x, l1.y, l1.z, l1.w};
    float bb[8] = {b0.x, b0.y, b0.z, b0.w, b1.x, b1.y, b1.z, b1.w};
    float sc[8], s4[8];
    #pragma unroll
    for (int i = 0; i < 8; i++) {
        float s = 1.0f / (1.0f + expf(-lv[i]));
        sc[i] = s;
        s4[i] = s + bb[i];
    }

    float m1 = -CUDART_INF_F, m2 = -CUDART_INF_F, m3 = -CUDART_INF_F;
    #pragma unroll
    for (int i = 0; i < 8; i++) {
        float v = s4[i];
        if (v > m1)      { m3 = m2; m2 = m1; m1 = v; }
        else if (v > m2) { m3 = m2; m2 = v; }
        else if (v > m3) { m3 = v; }
    }
    #pragma unroll
    for (int d = 1; d <= 2; d <<= 1) {
        float o1 = __shfl_xor_sync(FULL, m1, d);
        float o2 = __shfl_xor_sync(FULL, m2, d);
        float o3 = __shfl_xor_sync(FULL, m3, d);
        float mn1 = fminf(m1, o1);
        float mx2 = fmaxf(m2, o2);
        float n1 = fmaxf(m1, o1);
        float n2 = fmaxf(mn1, mx2);
        float n3 = fmaxf(fminf(mn1, mx2), fmaxf(m3, o3));
        m1 = n1; m2 = n2; m3 = n3;
    }
    const float gs  = m1 + m2;
    const float m23 = m2 - m3;
    const int   g   = lane >> 2;

    int rank = 0;
    #pragma unroll
    for (int j = 0; j < 8; j++) {
        float gj = __shfl_sync(FULL, gs, j * 4);
        rank += (gj > gs) || (gj == gs && j < g);
    }
    const int selg = (rank < 4);
    if (!selg) {
        #pragma unroll
        for (int i = 0; i < 8; i++) s4[i] = 0.0f;   // reference: score * mask
    }

    float flagmin = CUDART_INF_F;
    if (do_flag) {
        float vsel = selg ? gs : CUDART_INF_F;
        float vuns = selg ? -CUDART_INF_F : gs;
        float mm   = m23;
        #pragma unroll
        for (int d = 16; d; d >>= 1) {
            vsel = fminf(vsel, __shfl_xor_sync(FULL, vsel, d));
            vuns = fmaxf(vuns, __shfl_xor_sync(FULL, vuns, d));
            mm   = fminf(mm,   __shfl_xor_sync(FULL, mm,   d));
        }
        flagmin = fminf(vsel - vuns, mm);
    }

    float wsum = 0.0f, my_w = 0.0f, prevv = 0.0f;
    int   my_ix = 0;
    #pragma unroll
    for (int t = 0; t < 8; t++) {
        float bv = s4[0]; int bp = 0;
        #pragma unroll
        for (int i = 1; i < 8; i++)
            if (s4[i] > bv) { bv = s4[i]; bp = i; }
        float v  = bv;
        int   ix = lane * 8 + bp;
        #pragma unroll
        for (int d = 16; d; d >>= 1) {
            float ov = __shfl_xor_sync(FULL, v, d);
            int   oi = __shfl_xor_sync(FULL, ix, d);
            if (ov > v || (ov == v && oi < ix)) { v = ov; ix = oi; }
        }
        if (t > 0) flagmin = fminf(flagmin, prevv - v);
        prevv = v;
        const int opos  = ix & 7;
        const int olane = ix >> 3;
        #pragma unroll
        for (int i = 0; i < 8; i++)
            if (lane == olane && i == opos) s4[i] = -CUDART_INF_F;
        float cand = sc[0];
        #pragma unroll
        for (int i = 1; i < 8; i++)
            if (i == opos) cand = sc[i];
        float w = __shfl_sync(FULL, cand, olane);
        wsum += w;
        if (lane == t) { my_w = w; my_ix = ix; }
    }

    if (do_flag) {
        float bv = s4[0];
        #pragma unroll
        for (int i = 1; i < 8; i++) bv = fmaxf(bv, s4[i]);
        #pragma unroll
        for (int d = 16; d; d >>= 1)
            bv = fmaxf(bv, __shfl_xor_sync(FULL, bv, d));
        flagmin = fminf(flagmin, prevv - bv);
        if (lane == 0 && flagmin < TAU) {
            int p = atomicAdd(&g_nflag, 1);
            g_flagged[p] = token;
        }
    }

    const float scale = 2.5f / (wsum + 1e-20f);
    if (lane < TOPK) {
        out[(size_t)token * TOPK + lane] = my_w * scale;
        if (write_idx)
            out[(size_t)TOKENS * TOPK + (size_t)token * TOPK + lane] = (float)my_ix;
    }
}

// ---------------------------------------------------------------------------
__global__ __launch_bounds__(256)
void routing_kernel(const float* __restrict__ bias, float* __restrict__ out,
                    int write_idx)
{
    const int lane  = threadIdx.x & 31;
    const int warp  = threadIdx.x >> 5;
    const int token = blockIdx.x * 8 + warp;
    route_one(g_logits + (size_t)token * NEXP, bias, out, write_idx, token,
              lane, 1);
}

// ---------------------------------------------------------------------------
__global__ __launch_bounds__(256)
void recompute_kernel(const float* __restrict__ A, const float* __restrict__ W,
                      const float* __restrict__ bias, float* __restrict__ out,
                      int write_idx)
{
    __shared__ __align__(16) float srow[HIDDEN];
    __shared__ __align__(16) float slog[NEXP];

    const int nf   = g_nflag;
    const int wid  = threadIdx.x >> 5;
    const int lane = threadIdx.x & 31;

    for (int it = blockIdx.x; it < nf; it += gridDim.x) {
        const int token = g_flagged[it];
        for (int i = threadIdx.x * 4; i < HIDDEN; i += 1024)
            *(float4*)(srow + i) = *(const float4*)(A + (size_t)token * HIDDEN + i);
        __syncthreads();

        for (int e = wid * 32; e < wid * 32 + 32; e++) {
            const float* wr = W + (size_t)e * HIDDEN;
            float a0 = 0.f, a1 = 0.f;
            for (int i = lane * 4; i < HIDDEN; i += 256) {
                float4 wv = *(const float4*)(wr + i);
                float4 av = *(const float4*)(srow + i);
                a0 += av.x * wv.x + av.y * wv.y + av.z * wv.z + av.w * wv.w;
                float4 wv2 = *(const float4*)(wr + i + 128);
                float4 av2 = *(const float4*)(srow + i + 128);
                a1 += av2.x * wv2.x + av2.y * wv2.y + av2.z * wv2.z + av2.w * wv2.w;
            }
            float acc = a0 + a1;
            #pragma unroll
            for (int d = 16; d; d >>= 1)
                acc += __shfl_xor_sync(0xffffffffu, acc, d);
            if (lane == 0) slog[e] = acc;
        }
        __syncthreads();

        if (wid == 0)
            route_one(slog, bias, out, write_idx, token, lane, 0);
        __syncthreads();
    }
}

// ---------------------------------------------------------------------------
// Exactly 4 launches per call, gemm in slot 2: with ncu -s 5 -c 1, launch #6
// (= gemm of the second replay) is the one profiled.
// ---------------------------------------------------------------------------
extern "C" void kernel_launch(void* const* d_in, const int* in_sizes, int n_in,
                              void* d_out, int out_size)
{
    const float* hs   = (const float*)d_in[0];  // [16384, 7168]
    const float* w    = (const float*)d_in[1];  // [256, 7168]
    const float* bias = (const float*)d_in[2];  // [256]
    float* out = (float*)d_out;

    const int write_idx = (out_size >= TOKENS * TOPK * 2) ? 1 : 0;

    init_flags_kernel<<<1, 1>>>();
    dim3 ggrid(TOKENS / BM, NEXP / BN);   // (128, 2)
    gemm_kernel<<<ggrid, 256>>>(hs, w);
    routing_kernel<<<TOKENS / 8, 256>>>(bias, out, write_idx);
    recompute_kernel<<<128, 256>>>(hs, w, bias, out, write_idx);
}

// round 13
// speedup vs baseline: 1.0293x; 1.0293x over previous
#include <cuda_runtime.h>
#include <math_constants.h>
#include <math.h>
#include <cstdint>

#define TOKENS 16384
#define HIDDEN 7168
#define NEXP   256
#define TOPK   8
#define TAU    1e-4f

#define BM 128
#define BN 128
#define BK 8

__device__ float g_logits[(size_t)TOKENS * NEXP];
__device__ int   g_nflag;
__device__ int   g_flagged[TOKENS];

__global__ void init_flags_kernel() { g_nflag = 0; }

// ---------------------------------------------------------------------------
// Kernel: fp32 SGEMM — BYTE-IDENTICAL to the R1 kernel that measured 1337us.
// C[m][n] = sum_k A[m][k] * B[n][k]. 128x128 block tile, BK=8, 256 threads,
// 8x8 per-thread tile (4+4 split), single-sync double buffering.
// ---------------------------------------------------------------------------
__global__ __launch_bounds__(256)
void gemm_kernel(const float* __restrict__ A, const float* __restrict__ B)
{
    __shared__ float As[2][BK][BM];
    __shared__ float Bs[2][BK][BN];

    const int bm  = blockIdx.x * BM;
    const int bn  = blockIdx.y * BN;
    const int tid = threadIdx.x;
    const int tx  = tid & 15;   // 0..15 -> expert cols
    const int ty  = tid >> 4;   // 0..15 -> token rows

    // Global-load mapping: each thread loads one float4 of A and one of B
    const int ldrow = tid >> 1;        // 0..127
    const int ldcol = (tid & 1) * 4;   // 0 or 4

    const float* Aptr = A + (size_t)(bm + ldrow) * HIDDEN + ldcol;
    const float* Bptr = B + (size_t)(bn + ldrow) * HIDDEN + ldcol;

    float acc[8][8];
    #pragma unroll
    for (int i = 0; i < 8; i++)
        #pragma unroll
        for (int j = 0; j < 8; j++) acc[i][j] = 0.0f;

    // Preload tile 0
    {
        float4 a4 = *(const float4*)Aptr;
        float4 b4 = *(const float4*)Bptr;
        As[0][ldcol + 0][ldrow] = a4.x; As[0][ldcol + 1][ldrow] = a4.y;
        As[0][ldcol + 2][ldrow] = a4.z; As[0][ldcol + 3][ldrow] = a4.w;
        Bs[0][ldcol + 0][ldrow] = b4.x; Bs[0][ldcol + 1][ldrow] = b4.y;
        Bs[0][ldcol + 2][ldrow] = b4.z; Bs[0][ldcol + 3][ldrow] = b4.w;
    }
    __syncthreads();

    const int NK = HIDDEN / BK;  // 896
    int buf = 0;
    for (int kt = 0; kt < NK; kt++) {
        float4 na, nb;
        const bool has_next = (kt + 1 < NK);
        if (has_next) {
            na = *(const float4*)(Aptr + (size_t)(kt + 1) * BK);
            nb = *(const float4*)(Bptr + (size_t)(kt + 1) * BK);
        }
        #pragma unroll
        for (int k = 0; k < BK; k++) {
            float ar[8], br[8];
            *(float4*)&ar[0] = *(const float4*)&As[buf][k][ty * 4];
            *(float4*)&ar[4] = *(const float4*)&As[buf][k][ty * 4 + 64];
            *(float4*)&br[0] = *(const float4*)&Bs[buf][k][tx * 4];
            *(float4*)&br[4] = *(const float4*)&Bs[buf][k][tx * 4 + 64];
            #pragma unroll
            for (int i = 0; i < 8; i++)
                #pragma unroll
                for (int j = 0; j < 8; j++)
                    acc[i][j] += ar[i] * br[j];
        }
        if (has_next) {
            const int nbuf = buf ^ 1;
            As[nbuf][ldcol + 0][ldrow] = na.x; As[nbuf][ldcol + 1][ldrow] = na.y;
            As[nbuf][ldcol + 2][ldrow] = na.z; As[nbuf][ldcol + 3][ldrow] = na.w;
            Bs[nbuf][ldcol + 0][ldrow] = nb.x; Bs[nbuf][ldcol + 1][ldrow] = nb.y;
            Bs[nbuf][ldcol + 2][ldrow] = nb.z; Bs[nbuf][ldcol + 3][ldrow] = nb.w;
            __syncthreads();
            buf = nbuf;
        }
    }

    // Epilogue: rows ty*4+{0..3}, ty*4+64+{0..3}; cols tx*4+{0..3}, tx*4+64+{0..3}
    #pragma unroll
    for (int i = 0; i < 8; i++) {
        const int r = bm + ty * 4 + ((i < 4) ? i : (60 + i));  // i>=4 -> 64+(i-4)
        float* C = g_logits + (size_t)r * NEXP + bn;
        *(float4*)(C + tx * 4)      = make_float4(acc[i][0], acc[i][1], acc[i][2], acc[i][3]);
        *(float4*)(C + tx * 4 + 64) = make_float4(acc[i][4], acc[i][5], acc[i][6], acc[i][7]);
    }
}

// ---------------------------------------------------------------------------
// route_one: reference-exact routing for one token (validated R4-R12).
// ---------------------------------------------------------------------------
__device__ __forceinline__ void route_one(const float* __restrict__ row,
                                          const float* __restrict__ bias,
                                          float* __restrict__ out,
                                          int write_idx, int token, int lane,
                                          int do_flag)
{
    const unsigned FULL = 0xffffffffu;

    float4 l0 = *(const float4*)(row + lane * 8);
    float4 l1 = *(const float4*)(row + lane * 8 + 4);
    float4 b0 = *(const float4*)(bias + lane * 8);
    float4 b1 = *(const float4*)(bias + lane * 8 + 4);

    float lv[8] = {l0.x, l0.y, l0.z, l0.w, l1.x, l1.y, l1.z, l1.w};
    float bb[8] = {b0.x, b0.y, b0.z, b0.w, b1.x, b1.y, b1.z, b1.w};
    float sc[8], s4[8];
    #pragma unroll
    for (int i = 0; i < 8; i++) {
        float s = 1.0f / (1.0f + expf(-lv[i]));
        sc[i] = s;
        s4[i] = s + bb[i];
    }

    float m1 = -CUDART_INF_F, m2 = -CUDART_INF_F, m3 = -CUDART_INF_F;
    #pragma unroll
    for (int i = 0; i < 8; i++) {
        float v = s4[i];
        if (v > m1)      { m3 = m2; m2 = m1; m1 = v; }
        else if (v > m2) { m3 = m2; m2 = v; }
        else if (v > m3) { m3 = v; }
    }
    #pragma unroll
    for (int d = 1; d <= 2; d <<= 1) {
        float o1 = __shfl_xor_sync(FULL, m1, d);
        float o2 = __shfl_xor_sync(FULL, m2, d);
        float o3 = __shfl_xor_sync(FULL, m3, d);
        float mn1 = fminf(m1, o1);
        float mx2 = fmaxf(m2, o2);
        float n1 = fmaxf(m1, o1);
        float n2 = fmaxf(mn1, mx2);
        float n3 = fmaxf(fminf(mn1, mx2), fmaxf(m3, o3));
        m1 = n1; m2 = n2; m3 = n3;
    }
    const float gs  = m1 + m2;
    const float m23 = m2 - m3;
    const int   g   = lane >> 2;

    int rank = 0;
    #pragma unroll
    for (int j = 0; j < 8; j++) {
        float gj = __shfl_sync(FULL, gs, j * 4);
        rank += (gj > gs) || (gj == gs && j < g);
    }
    const int selg = (rank < 4);
    if (!selg) {
        #pragma unroll
        for (int i = 0; i < 8; i++) s4[i] = 0.0f;   // reference: score * mask
    }

    float flagmin = CUDART_INF_F;
    if (do_flag) {
        float vsel = selg ? gs : CUDART_INF_F;
        float vuns = selg ? -CUDART_INF_F : gs;
        float mm   = m23;
        #pragma unroll
        for (int d = 16; d; d >>= 1) {
            vsel = fminf(vsel, __shfl_xor_sync(FULL, vsel, d));
            vuns = fmaxf(vuns, __shfl_xor_sync(FULL, vuns, d));
            mm   = fminf(mm,   __shfl_xor_sync(FULL, mm,   d));
        }
        flagmin = fminf(vsel - vuns, mm);
    }

    float wsum = 0.0f, my_w = 0.0f, prevv = 0.0f;
    int   my_ix = 0;
    #pragma unroll
    for (int t = 0; t < 8; t++) {
        float bv = s4[0]; int bp = 0;
        #pragma unroll
        for (int i = 1; i < 8; i++)
            if (s4[i] > bv) { bv = s4[i]; bp = i; }
        float v  = bv;
        int   ix = lane * 8 + bp;
        #pragma unroll
        for (int d = 16; d; d >>= 1) {
            float ov = __shfl_xor_sync(FULL, v, d);
            int   oi = __shfl_xor_sync(FULL, ix, d);
            if (ov > v || (ov == v && oi < ix)) { v = ov; ix = oi; }
        }
        if (t > 0) flagmin = fminf(flagmin, prevv - v);
        prevv = v;
        const int opos  = ix & 7;
        const int olane = ix >> 3;
        #pragma unroll
        for (int i = 0; i < 8; i++)
            if (lane == olane && i == opos) s4[i] = -CUDART_INF_F;
        float cand = sc[0];
        #pragma unroll
        for (int i = 1; i < 8; i++)
            if (i == opos) cand = sc[i];
        float w = __shfl_sync(FULL, cand, olane);
        wsum += w;
        if (lane == t) { my_w = w; my_ix = ix; }
    }

    if (do_flag) {
        float bv = s4[0];
        #pragma unroll
        for (int i = 1; i < 8; i++) bv = fmaxf(bv, s4[i]);
        #pragma unroll
        for (int d = 16; d; d >>= 1)
            bv = fmaxf(bv, __shfl_xor_sync(FULL, bv, d));
        flagmin = fminf(flagmin, prevv - bv);
        if (lane == 0 && flagmin < TAU) {
            int p = atomicAdd(&g_nflag, 1);
            g_flagged[p] = token;
        }
    }

    const float scale = 2.5f / (wsum + 1e-20f);
    if (lane < TOPK) {
        out[(size_t)token * TOPK + lane] = my_w * scale;
        if (write_idx)
            out[(size_t)TOKENS * TOPK + (size_t)token * TOPK + lane] = (float)my_ix;
    }
}

// ---------------------------------------------------------------------------
__global__ __launch_bounds__(256)
void routing_kernel(const float* __restrict__ bias, float* __restrict__ out,
                    int write_idx)
{
    const int lane  = threadIdx.x & 31;
    const int warp  = threadIdx.x >> 5;
    const int token = blockIdx.x * 8 + warp;
    route_one(g_logits + (size_t)token * NEXP, bias, out, write_idx, token,
              lane, 1);
}

// ---------------------------------------------------------------------------
__global__ __launch_bounds__(256)
void recompute_kernel(const float* __restrict__ A, const float* __restrict__ W,
                      const float* __restrict__ bias, float* __restrict__ out,
                      int write_idx)
{
    __shared__ __align__(16) float srow[HIDDEN];
    __shared__ __align__(16) float slog[NEXP];

    const int nf   = g_nflag;
    const int wid  = threadIdx.x >> 5;
    const int lane = threadIdx.x & 31;

    for (int it = blockIdx.x; it < nf; it += gridDim.x) {
        const int token = g_flagged[it];
        for (int i = threadIdx.x * 4; i < HIDDEN; i += 1024)
            *(float4*)(srow + i) = *(const float4*)(A + (size_t)token * HIDDEN + i);
        __syncthreads();

        for (int e = wid * 32; e < wid * 32 + 32; e++) {
            const float* wr = W + (size_t)e * HIDDEN;
            float a0 = 0.f, a1 = 0.f;
            for (int i = lane * 4; i < HIDDEN; i += 256) {
                float4 wv = *(const float4*)(wr + i);
                float4 av = *(const float4*)(srow + i);
                a0 += av.x * wv.x + av.y * wv.y + av.z * wv.z + av.w * wv.w;
                float4 wv2 = *(const float4*)(wr + i + 128);
                float4 av2 = *(const float4*)(srow + i + 128);
                a1 += av2.x * wv2.x + av2.y * wv2.y + av2.z * wv2.z + av2.w * wv2.w;
            }
            float acc = a0 + a1;
            #pragma unroll
            for (int d = 16; d; d >>= 1)
                acc += __shfl_xor_sync(0xffffffffu, acc, d);
            if (lane == 0) slog[e] = acc;
        }
        __syncthreads();

        if (wid == 0)
            route_one(slog, bias, out, write_idx, token, lane, 0);
        __syncthreads();
    }
}

// ---------------------------------------------------------------------------
extern "C" void kernel_launch(void* const* d_in, const int* in_sizes, int n_in,
                              void* d_out, int out_size)
{
    const float* hs   = (const float*)d_in[0];  // [16384, 7168]
    const float* w    = (const float*)d_in[1];  // [256, 7168]
    const float* bias = (const float*)d_in[2];  // [256]
    float* out = (float*)d_out;

    const int write_idx = (out_size >= TOKENS * TOPK * 2) ? 1 : 0;

    init_flags_kernel<<<1, 1>>>();
    dim3 ggrid(TOKENS / BM, NEXP / BN);   // (128, 2)
    gemm_kernel<<<ggrid, 256>>>(hs, w);
    routing_kernel<<<TOKENS / 8, 256>>>(bias, out, write_idx);
    recompute_kernel<<<128, 256>>>(hs, w, bias, out, write_idx);
}

// round 14
// speedup vs baseline: 1.4476x; 1.4064x over previous
#include <cuda_runtime.h>
#include <cuda_bf16.h>
#include <math_constants.h>
#include <math.h>
#include <cstdint>

#define TOKENS 16384
#define HIDDEN 7168
#define NEXP   256
#define TOPK   8
#define KC     32
#define NCH    (HIDDEN / KC)   // 224
#define TAU    1e-4f

// SMEM per stage: Ah 8K | Al 8K | Bh 16K | Bl 16K = 48KB
#define ST_BYTES 49152
#define OFF_AH   0
#define OFF_AL   8192
#define OFF_BH   16384
#define OFF_BL   32768
#define SMEM_TOTAL (2 * ST_BYTES)

// chunk-blocked swizzle-baked bf16 weights: [ch][n][64B]
__device__ uint32_t g_Bh[(size_t)NEXP * HIDDEN / 2];
__device__ uint32_t g_Bl[(size_t)NEXP * HIDDEN / 2];
__device__ float    g_logits[(size_t)TOKENS * NEXP];
__device__ int      g_nflag;
__device__ int      g_flagged[TOKENS];

__device__ __forceinline__ uint32_t pack_bf2(float lo, float hi) {
    __nv_bfloat162 t = __floats2bfloat162_rn(lo, hi);
    return *reinterpret_cast<uint32_t*>(&t);
}

#define CPA16(dst, src) \
    asm volatile("cp.async.cg.shared.global [%0], [%1], 16;" \
                 :: "r"(dst), "l"(src) : "memory")

#define LDSM4(r, addr) \
    asm volatile("ldmatrix.sync.aligned.m8n8.x4.shared.b16 {%0,%1,%2,%3}, [%4];" \
                 : "=r"((r)[0]), "=r"((r)[1]), "=r"((r)[2]), "=r"((r)[3]) \
                 : "r"(addr))

#define MMA_BF16(cp, a, B0, B1) \
    asm volatile("mma.sync.aligned.m16n8k16.row.col.f32.bf16.bf16.f32 " \
                 "{%0,%1,%2,%3},{%4,%5,%6,%7},{%8,%9},{%0,%1,%2,%3};" \
                 : "+f"((cp)[0]), "+f"((cp)[1]), "+f"((cp)[2]), "+f"((cp)[3]) \
                 : "r"((a)[0]), "r"((a)[1]), "r"((a)[2]), "r"((a)[3]), \
                   "r"(B0), "r"(B1))

// ---------------------------------------------------------------------------
// Kernel 0: split W fp32 -> bf16 hi/lo, chunk-blocked + swizzle baked
// (validated R7: rel_err 2.19e-6 end-to-end).
// ---------------------------------------------------------------------------
__global__ __launch_bounds__(256)
void convert_b_kernel(const float* __restrict__ W) {
    if (blockIdx.x == 0 && threadIdx.x == 0) g_nflag = 0;

    const int ch = blockIdx.x;
    const int n  = threadIdx.x;
    const float* src = W + (size_t)n * HIDDEN + ch * KC;

    float v[32];
    #pragma unroll
    for (int j = 0; j < 8; j++) {
        float4 t = *(const float4*)(src + 4 * j);
        v[4 * j] = t.x; v[4 * j + 1] = t.y; v[4 * j + 2] = t.z; v[4 * j + 3] = t.w;
    }
    uint32_t hw[16], lw[16];
    #pragma unroll
    for (int k = 0; k < 16; k++) {
        float a0 = v[2 * k], a1 = v[2 * k + 1];
        __nv_bfloat16 h0 = __float2bfloat16_rn(a0);
        __nv_bfloat16 h1 = __float2bfloat16_rn(a1);
        hw[k] = pack_bf2(__bfloat162float(h0), __bfloat162float(h1));
        lw[k] = pack_bf2(a0 - __bfloat162float(h0), a1 - __bfloat162float(h1));
    }
    char* dh = (char*)g_Bh + (size_t)ch * (NEXP * 64) + n * 64;
    char* dl = (char*)g_Bl + (size_t)ch * (NEXP * 64) + n * 64;
    const int swn = (n >> 1) & 3;
    #pragma unroll
    for (int s = 0; s < 4; s++) {
        const int so = (s ^ swn) * 16;
        *(uint4*)(dh + so) = make_uint4(hw[4*s], hw[4*s+1], hw[4*s+2], hw[4*s+3]);
        *(uint4*)(dl + so) = make_uint4(lw[4*s], lw[4*s+1], lw[4*s+2], lw[4*s+3]);
    }
}

// ---------------------------------------------------------------------------
// Kernel 1: 3-term bf16-split GEMM — R7's kernel at DOUBLE occupancy.
// One 512-thread CTA (16 warps, 4/SMSP), grid 128 single wave.
// Warps 4x4: warp tile 32x64, cc[2][8][4] = 64 accums (~115 regs, no spill).
// logits = Ah*Bh + Al*Bh + Ah*Bl, fp32 accum.
// ---------------------------------------------------------------------------
__global__ __launch_bounds__(512, 1)
void gemm_bf16(const float* __restrict__ A)
{
    extern __shared__ char smem[];
    uint32_t sb;
    asm("{ .reg .u64 t; cvta.to.shared.u64 t, %1; cvt.u32.u64 %0, t; }"
        : "=r"(sb) : "l"((void*)smem));

    const int tid  = threadIdx.x;
    const int lane = tid & 31;
    const int wid  = tid >> 5;
    const int wm   = wid >> 2;          // 0..3 (32-row band)
    const int wn   = wid & 3;           // 0..3 (64-col band)
    const int bm   = blockIdx.x * 128;

    // ldmatrix lane address components (identical math to R7)
    const int rowin = ((lane >> 3) & 1) * 8 + (lane & 7);
    const int kqa   = lane >> 4;
    const int swa   = (rowin >> 1) & 3;
    const int nin   = ((lane >> 4) & 1) * 8 + (lane & 7);
    const int kqb   = (lane >> 3) & 1;
    const int swb   = (nin >> 1) & 3;
    const uint32_t arowoff = (uint32_t)(wm * 32 + rowin) * 64;
    const uint32_t browoff = (uint32_t)(wn * 64 + nin) * 64;

    // A loader: 4 threads/row, 8 k each
    const int arow  = tid >> 2;         // 0..127
    const int apart = tid & 3;          // k octet: 8*apart..+7
    const int swr   = (arow >> 1) & 3;
    const float* Agp = A + (size_t)(bm + arow) * HIDDEN + apart * 8;
    // B loader: 2 threads/row, 32B each
    const int brow  = tid >> 1;         // 0..255
    const int bhalf = tid & 1;

    float cc[2][8][4];
    #pragma unroll
    for (int i = 0; i < 2; i++)
        #pragma unroll
        for (int j = 0; j < 8; j++)
            #pragma unroll
            for (int q = 0; q < 4; q++) cc[i][j][q] = 0.0f;

#define LOAD_B_ASYNC(nc, st) do {                                              \
        const char* __sh = (const char*)g_Bh + (size_t)(nc) * (NEXP * 64)      \
                           + brow * 64 + bhalf * 32;                           \
        const char* __sl = (const char*)g_Bl + (size_t)(nc) * (NEXP * 64)      \
                           + brow * 64 + bhalf * 32;                           \
        uint32_t __dh = sb + (st) * ST_BYTES + OFF_BH + brow * 64 + bhalf * 32;\
        uint32_t __dl = sb + (st) * ST_BYTES + OFF_BL + brow * 64 + bhalf * 32;\
        CPA16(__dh,      __sh);                                                \
        CPA16(__dh + 16, __sh + 16);                                           \
        CPA16(__dl,      __sl);                                                \
        CPA16(__dl + 16, __sl + 16);                                           \
        asm volatile("cp.async.commit_group;" ::: "memory");                   \
    } while (0)

#define LOAD_A_LDG(nc, va) do {                                                \
        const float* __p = Agp + (size_t)(nc) * KC;                            \
        float4 t0 = __ldg((const float4*)__p);                                 \
        float4 t1 = __ldg((const float4*)(__p + 4));                           \
        (va)[0] = t0.x; (va)[1] = t0.y; (va)[2] = t0.z; (va)[3] = t0.w;        \
        (va)[4] = t1.x; (va)[5] = t1.y; (va)[6] = t1.z; (va)[7] = t1.w;        \
    } while (0)

#define STORE_A(st, va) do {                                                   \
        uint32_t h[4], l[4];                                                   \
        _Pragma("unroll")                                                      \
        for (int k = 0; k < 4; k++) {                                          \
            float a0 = (va)[2*k], a1 = (va)[2*k+1];                            \
            __nv_bfloat16 h0 = __float2bfloat16_rn(a0);                        \
            __nv_bfloat16 h1 = __float2bfloat16_rn(a1);                        \
            h[k] = pack_bf2(__bfloat162float(h0), __bfloat162float(h1));       \
            l[k] = pack_bf2(a0 - __bfloat162float(h0),                         \
                            a1 - __bfloat162float(h1));                        \
        }                                                                      \
        const uint32_t __off = (st) * ST_BYTES + arow * 64 +                   \
                               ((apart ^ swr) << 4);                           \
        *(uint4*)(smem + __off + OFF_AH) = make_uint4(h[0], h[1], h[2], h[3]); \
        *(uint4*)(smem + __off + OFF_AL) = make_uint4(l[0], l[1], l[2], l[3]); \
    } while (0)

    // ---- prologue ----
    {
        LOAD_B_ASYNC(0, 0);
        float va[8];
        LOAD_A_LDG(0, va);
        STORE_A(0, va);
        asm volatile("cp.async.wait_group 0;" ::: "memory");
        __syncthreads();
    }

    // ---- main loop ----
    for (int c = 0; c < NCH; c++) {
        const int s   = c & 1;
        const bool np = (c + 1 < NCH);
        float va[8];
        if (np) {
            LOAD_B_ASYNC(c + 1, s ^ 1);
            LOAD_A_LDG(c + 1, va);
        }

        const uint32_t base = sb + s * ST_BYTES;
        #pragma unroll
        for (int H = 0; H < 2; H++) {
            const uint32_t aseg = (uint32_t)((((H << 1) | kqa) ^ swa) * 16);
            const uint32_t bseg = (uint32_t)((((H << 1) | kqb) ^ swb) * 16);
            uint32_t ah[2][4], al[2][4], bf[4][4];
            #pragma unroll
            for (int mb = 0; mb < 2; mb++)
                LDSM4(ah[mb], base + OFF_AH + arowoff + mb * 1024 + aseg);
            #pragma unroll
            for (int pr = 0; pr < 4; pr++)
                LDSM4(bf[pr], base + OFF_BH + browoff + pr * 1024 + bseg);
            #pragma unroll
            for (int mb = 0; mb < 2; mb++)
                #pragma unroll
                for (int pr = 0; pr < 4; pr++) {
                    MMA_BF16(cc[mb][2*pr],     ah[mb], bf[pr][0], bf[pr][1]);
                    MMA_BF16(cc[mb][2*pr + 1], ah[mb], bf[pr][2], bf[pr][3]);
                }
            #pragma unroll
            for (int mb = 0; mb < 2; mb++)
                LDSM4(al[mb], base + OFF_AL + arowoff + mb * 1024 + aseg);
            #pragma unroll
            for (int mb = 0; mb < 2; mb++)
                #pragma unroll
                for (int pr = 0; pr < 4; pr++) {
                    MMA_BF16(cc[mb][2*pr],     al[mb], bf[pr][0], bf[pr][1]);
                    MMA_BF16(cc[mb][2*pr + 1], al[mb], bf[pr][2], bf[pr][3]);
                }
            #pragma unroll
            for (int pr = 0; pr < 4; pr++)
                LDSM4(bf[pr], base + OFF_BL + browoff + pr * 1024 + bseg);
            #pragma unroll
            for (int mb = 0; mb < 2; mb++)
                #pragma unroll
                for (int pr = 0; pr < 4; pr++) {
                    MMA_BF16(cc[mb][2*pr],     ah[mb], bf[pr][0], bf[pr][1]);
                    MMA_BF16(cc[mb][2*pr + 1], ah[mb], bf[pr][2], bf[pr][3]);
                }
        }

        if (np) {
            STORE_A(s ^ 1, va);
            asm volatile("cp.async.wait_group 0;" ::: "memory");
        }
        __syncthreads();
    }

    // ---- epilogue ----
    const int lq = lane >> 2;
    const int lr = lane & 3;
    #pragma unroll
    for (int mb = 0; mb < 2; mb++) {
        const int r0 = bm + wm * 32 + mb * 16 + lq;
        #pragma unroll
        for (int nb = 0; nb < 8; nb++) {
            const int col = wn * 64 + nb * 8 + 2 * lr;
            *(float2*)(g_logits + (size_t)r0 * NEXP + col) =
                make_float2(cc[mb][nb][0], cc[mb][nb][1]);
            *(float2*)(g_logits + (size_t)(r0 + 8) * NEXP + col) =
                make_float2(cc[mb][nb][2], cc[mb][nb][3]);
        }
    }
}

// ---------------------------------------------------------------------------
// route_one: reference-exact routing for one token (validated R4-R13).
// ---------------------------------------------------------------------------
__device__ __forceinline__ void route_one(const float* __restrict__ row,
                                          const float* __restrict__ bias,
                                          float* __restrict__ out,
                                          int write_idx, int token, int lane,
                                          int do_flag)
{
    const unsigned FULL = 0xffffffffu;

    float4 l0 = *(const float4*)(row + lane * 8);
    float4 l1 = *(const float4*)(row + lane * 8 + 4);
    float4 b0 = *(const float4*)(bias + lane * 8);
    float4 b1 = *(const float4*)(bias + lane * 8 + 4);

    float lv[8] = {l0.x, l0.y, l0.z, l0.w, l1.x, l1.y, l1.z, l1.w};
    float bb[8] = {b0.x, b0.y, b0.z, b0.w, b1.x, b1.y, b1.z, b1.w};
    float sc[8], s4[8];
    #pragma unroll
    for (int i = 0; i < 8; i++) {
        float s = 1.0f / (1.0f + expf(-lv[i]));
        sc[i] = s;
        s4[i] = s + bb[i];
    }

    float m1 = -CUDART_INF_F, m2 = -CUDART_INF_F, m3 = -CUDART_INF_F;
    #pragma unroll
    for (int i = 0; i < 8; i++) {
        float v = s4[i];
        if (v > m1)      { m3 = m2; m2 = m1; m1 = v; }
        else if (v > m2) { m3 = m2; m2 = v; }
        else if (v > m3) { m3 = v; }
    }
    #pragma unroll
    for (int d = 1; d <= 2; d <<= 1) {
        float o1 = __shfl_xor_sync(FULL, m1, d);
        float o2 = __shfl_xor_sync(FULL, m2, d);
        float o3 = __shfl_xor_sync(FULL, m3, d);
        float mn1 = fminf(m1, o1);
        float mx2 = fmaxf(m2, o2);
        float n1 = fmaxf(m1, o1);
        float n2 = fmaxf(mn1, mx2);
        float n3 = fmaxf(fminf(mn1, mx2), fmaxf(m3, o3));
        m1 = n1; m2 = n2; m3 = n3;
    }
    const float gs  = m1 + m2;
    const float m23 = m2 - m3;
    const int   g   = lane >> 2;

    int rank = 0;
    #pragma unroll
    for (int j = 0; j < 8; j++) {
        float gj = __shfl_sync(FULL, gs, j * 4);
        rank += (gj > gs) || (gj == gs && j < g);
    }
    const int selg = (rank < 4);
    if (!selg) {
        #pragma unroll
        for (int i = 0; i < 8; i++) s4[i] = 0.0f;   // reference: score * mask
    }

    float flagmin = CUDART_INF_F;
    if (do_flag) {
        float vsel = selg ? gs : CUDART_INF_F;
        float vuns = selg ? -CUDART_INF_F : gs;
        float mm   = m23;
        #pragma unroll
        for (int d = 16; d; d >>= 1) {
            vsel = fminf(vsel, __shfl_xor_sync(FULL, vsel, d));
            vuns = fmaxf(vuns, __shfl_xor_sync(FULL, vuns, d));
            mm   = fminf(mm,   __shfl_xor_sync(FULL, mm,   d));
        }
        flagmin = fminf(vsel - vuns, mm);
    }

    float wsum = 0.0f, my_w = 0.0f, prevv = 0.0f;
    int   my_ix = 0;
    #pragma unroll
    for (int t = 0; t < 8; t++) {
        float bv = s4[0]; int bp = 0;
        #pragma unroll
        for (int i = 1; i < 8; i++)
            if (s4[i] > bv) { bv = s4[i]; bp = i; }
        float v  = bv;
        int   ix = lane * 8 + bp;
        #pragma unroll
        for (int d = 16; d; d >>= 1) {
            float ov = __shfl_xor_sync(FULL, v, d);
            int   oi = __shfl_xor_sync(FULL, ix, d);
            if (ov > v || (ov == v && oi < ix)) { v = ov; ix = oi; }
        }
        if (t > 0) flagmin = fminf(flagmin, prevv - v);
        prevv = v;
        const int opos  = ix & 7;
        const int olane = ix >> 3;
        #pragma unroll
        for (int i = 0; i < 8; i++)
            if (lane == olane && i == opos) s4[i] = -CUDART_INF_F;
        float cand = sc[0];
        #pragma unroll
        for (int i = 1; i < 8; i++)
            if (i == opos) cand = sc[i];
        float w = __shfl_sync(FULL, cand, olane);
        wsum += w;
        if (lane == t) { my_w = w; my_ix = ix; }
    }

    if (do_flag) {
        float bv = s4[0];
        #pragma unroll
        for (int i = 1; i < 8; i++) bv = fmaxf(bv, s4[i]);
        #pragma unroll
        for (int d = 16; d; d >>= 1)
            bv = fmaxf(bv, __shfl_xor_sync(FULL, bv, d));
        flagmin = fminf(flagmin, prevv - bv);
        if (lane == 0 && flagmin < TAU) {
            int p = atomicAdd(&g_nflag, 1);
            g_flagged[p] = token;
        }
    }

    const float scale = 2.5f / (wsum + 1e-20f);
    if (lane < TOPK) {
        out[(size_t)token * TOPK + lane] = my_w * scale;
        if (write_idx)
            out[(size_t)TOKENS * TOPK + (size_t)token * TOPK + lane] = (float)my_ix;
    }
}

// ---------------------------------------------------------------------------
__global__ __launch_bounds__(256)
void routing_kernel(const float* __restrict__ bias, float* __restrict__ out,
                    int write_idx)
{
    const int lane  = threadIdx.x & 31;
    const int warp  = threadIdx.x >> 5;
    const int token = blockIdx.x * 8 + warp;
    route_one(g_logits + (size_t)token * NEXP, bias, out, write_idx, token,
              lane, 1);
}

// ---------------------------------------------------------------------------
__global__ __launch_bounds__(256)
void recompute_kernel(const float* __restrict__ A, const float* __restrict__ W,
                      const float* __restrict__ bias, float* __restrict__ out,
                      int write_idx)
{
    __shared__ __align__(16) float srow[HIDDEN];
    __shared__ __align__(16) float slog[NEXP];

    const int nf   = g_nflag;
    const int wid  = threadIdx.x >> 5;
    const int lane = threadIdx.x & 31;

    for (int it = blockIdx.x; it < nf; it += gridDim.x) {
        const int token = g_flagged[it];
        for (int i = threadIdx.x * 4; i < HIDDEN; i += 1024)
            *(float4*)(srow + i) = *(const float4*)(A + (size_t)token * HIDDEN + i);
        __syncthreads();

        for (int e = wid * 32; e < wid * 32 + 32; e++) {
            const float* wr = W + (size_t)e * HIDDEN;
            float a0 = 0.f, a1 = 0.f;
            for (int i = lane * 4; i < HIDDEN; i += 256) {
                float4 wv = *(const float4*)(wr + i);
                float4 av = *(const float4*)(srow + i);
                a0 += av.x * wv.x + av.y * wv.y + av.z * wv.z + av.w * wv.w;
                float4 wv2 = *(const float4*)(wr + i + 128);
                float4 av2 = *(const float4*)(srow + i + 128);
                a1 += av2.x * wv2.x + av2.y * wv2.y + av2.z * wv2.z + av2.w * wv2.w;
            }
            float acc = a0 + a1;
            #pragma unroll
            for (int d = 16; d; d >>= 1)
                acc += __shfl_xor_sync(0xffffffffu, acc, d);
            if (lane == 0) slog[e] = acc;
        }
        __syncthreads();

        if (wid == 0)
            route_one(slog, bias, out, write_idx, token, lane, 0);
        __syncthreads();
    }
}

// ---------------------------------------------------------------------------
extern "C" void kernel_launch(void* const* d_in, const int* in_sizes, int n_in,
                              void* d_out, int out_size)
{
    const float* hs   = (const float*)d_in[0];  // [16384, 7168]
    const float* w    = (const float*)d_in[1];  // [256, 7168]
    const float* bias = (const float*)d_in[2];  // [256]
    float* out = (float*)d_out;

    cudaFuncSetAttribute(gemm_bf16,
                         cudaFuncAttributeMaxDynamicSharedMemorySize,
                         SMEM_TOTAL);

    convert_b_kernel<<<NCH, 256>>>(w);
    gemm_bf16<<<TOKENS / 128, 512, SMEM_TOTAL>>>(hs);

    const int write_idx = (out_size >= TOKENS * TOPK * 2) ? 1 : 0;
    routing_kernel<<<TOKENS / 8, 256>>>(bias, out, write_idx);
    recompute_kernel<<<128, 256>>>(hs, w, bias, out, write_idx);
}